// round 14
// baseline (speedup 1.0000x reference)
#include <cuda_runtime.h>

#define CC   10
#define HH   30
#define WW   30
#define DD   11
#define FULL 0xFFFFFFFFu

__device__ __forceinline__ float rsum16(float v) {
    #pragma unroll
    for (int o = 1; o < 16; o <<= 1) v += __shfl_xor_sync(FULL, v, o);
    return v;
}

__global__ __launch_bounds__(128, 10) void pve_kernel(
    const float* __restrict__ x,      // [2,10,30,30] one-hot
    const float* __restrict__ w_in,   // [33,11]
    const float* __restrict__ w_out,  // [11,11]
    const float* __restrict__ w_ff1,  // [1,11]
    const float* __restrict__ w_ff2,  // [11,1]
    const float* __restrict__ ln1_g,  // [11]
    const float* __restrict__ ln2_g,  // [11]
    float* __restrict__ out)          // [1800,10,100]
{
    __shared__ float pvs[10];

    const int tid  = threadIdx.x;     // 0..127
    const int lane = tid & 31;
    const int wrp  = tid >> 5;
    const int b    = blockIdx.x;      // pixel id 0..1799
    const int n    = b / 900;
    const int rem  = b % 900;
    const int pi   = rem / 30, pj = rem % 30;

    const bool haspad = (pi < 4) | (pi > HH - 5) | (pj < 4) | (pj > WW - 5);

    // window/image geometry (valid window rows/cols)
    const int r0 = max(0, 4 - pi), r1 = min(8, 33 - pi);
    const int c0 = max(0, 4 - pj), c1 = min(8, 33 - pj);

    // ── border pipeline on warp 0: histogram straight from x, then 11-dim chain ──
    if (haspad && wrp == 0) {
        const int d = lane;

        // lane c (<10) sums its one-hot plane over the valid window = hist[c]
        float h = 0.f;
        if (d < CC) {
            const float* xp = x + (long)n * 9000 + d * 900 + (pi - 4) * 30 + (pj - 4);
            for (int mh = r0; mh <= r1; mh++) {
                const float* rowp = xp + mh * 30;
                for (int mw = c0; mw <= c1; mw++) h += rowp[mw];
            }
        }
        // broadcast counts to all lanes
        float hf[DD];
        #pragma unroll
        for (int c = 0; c < CC; c++) hf[c] = __shfl_sync(FULL, h, c);
        hf[10] = (float)(81 - (r1 - r0 + 1) * (c1 - c0 + 1));

        // attention for the padding-class query; lane d owns dim d
        float num = 0.f, den = 0.f;
        if (d < DD) {
            float q10 = w_in[d * DD + 10];
            #pragma unroll
            for (int c = 0; c < DD; c++) {
                float k = w_in[(DD + d) * DD + c];
                float v = w_in[(2 * DD + d) * DD + c];
                float e = __expf(q10 * k) * hf[c];
                den += e;
                num += e * v;
            }
        }
        float ao = (d < DD) ? num / den : 0.f;

        // svec = e_10 + ao @ w_out^T
        float acc = (d == 10) ? 1.f : 0.f;
        #pragma unroll
        for (int c = 0; c < DD; c++) {
            float a = __shfl_sync(FULL, ao, c);
            if (d < DD) acc += a * w_out[d * DD + c];
        }
        float sv = (d < DD) ? acc : 0.f;

        // LN1 (mean & E[x^2], independent reduction chains)
        float s1 = rsum16(sv);
        float s2 = rsum16(sv * sv);
        float m   = s1 * (1.f / 11.f);
        float var = fmaxf(s2 * (1.f / 11.f) - m * m, 0.f);
        float inv = rsqrtf(var + 1e-5f);
        float h1  = (d < DD) ? (sv - m) * inv * ln1_g[d] : 0.f;

        // FF
        float tt = rsum16((d < DD) ? h1 * w_ff1[d] : 0.f);
        tt = fmaxf(tt, 0.f);
        float h2 = (d < DD) ? h1 + tt * w_ff2[d] : 0.f;

        // LN2
        float t1 = rsum16(h2);
        float t2 = rsum16(h2 * h2);
        float m2   = t1 * (1.f / 11.f);
        float var2 = fmaxf(t2 * (1.f / 11.f) - m2 * m2, 0.f);
        float inv2 = rsqrtf(var2 + 1e-5f);
        float hhv  = (d < DD) ? (h2 - m2) * inv2 * ln2_g[d] : 0.f;

        // softmax over classes 0..9 (post-LN values bounded: no max-sub)
        float ex = (d < CC) ? __expf(hhv) : 0.f;
        float se = rsum16(ex);
        if (d < CC) pvs[d] = ex / se;
    }
    if (haspad) __syncthreads();   // uniform per block: legal

    // ── direct gather-scatter: 250 float4 per pixel, no staging ──
    // out element (c, l): l = mh*10+mw. masked (mh==9||mw==9) -> 0;
    // in-image -> x[n,c,si,sj]; else (border only) -> pvs[c].
    float4* o4 = reinterpret_cast<float4*>(out + (long)b * 1000);
    const float* xb = x + (long)n * 9000 + (pi - 4) * 30 + (pj - 4);
    #pragma unroll
    for (int it = 0; it < 2; it++) {
        int q = tid + it * 128;
        if (q < 250) {
            int c = q / 25;
            int j = q - c * 25;
            float pc = haspad ? pvs[c] : 0.f;
            const float* xc = xb + c * 900;
            float4 r;
            float* rp = &r.x;
            #pragma unroll
            for (int e = 0; e < 4; e++) {
                int l  = 4 * j + e;
                int mh = l / 10;
                int mw = l - 10 * mh;
                bool masked = (mh == 9) | (mw == 9);
                bool inimg  = (mh >= r0) & (mh <= r1) & (mw >= c0) & (mw <= c1);
                float val = 0.f;
                if (!masked) val = inimg ? xc[mh * 30 + mw] : pc;
                rp[e] = val;
            }
            o4[q] = r;
        }
    }
}

extern "C" void kernel_launch(void* const* d_in, const int* in_sizes, int n_in,
                              void* d_out, int out_size) {
    const float* x     = (const float*)d_in[0];
    const float* w_in  = (const float*)d_in[1];
    const float* w_out = (const float*)d_in[2];
    const float* w_ff1 = (const float*)d_in[3];
    const float* w_ff2 = (const float*)d_in[4];
    const float* ln1_g = (const float*)d_in[5];
    const float* ln2_g = (const float*)d_in[6];

    pve_kernel<<<1800, 128>>>(x, w_in, w_out, w_ff1, w_ff2, ln1_g, ln2_g,
                              (float*)d_out);
}

// round 17
// speedup vs baseline: 1.0570x; 1.0570x over previous
#include <cuda_runtime.h>

#define CC   10
#define HH   30
#define WW   30
#define DD   11
#define FULL 0xFFFFFFFFu

__device__ __forceinline__ float rsum16(float v) {
    #pragma unroll
    for (int o = 1; o < 16; o <<= 1) v += __shfl_xor_sync(FULL, v, o);
    return v;
}

__global__ __launch_bounds__(128, 12) void pve_kernel(
    const float* __restrict__ x,      // [2,10,30,30] one-hot
    const float* __restrict__ w_in,   // [33,11]
    const float* __restrict__ w_out,  // [11,11]
    const float* __restrict__ w_ff1,  // [1,11]
    const float* __restrict__ w_ff2,  // [11,1]
    const float* __restrict__ ln1_g,  // [11]
    const float* __restrict__ ln2_g,  // [11]
    float* __restrict__ out)          // [1800,10,100]
{
    __shared__ union { unsigned char b[100]; unsigned int w[25]; } wtab;
    __shared__ float pvs[10];

    const int tid  = threadIdx.x;     // 0..127
    const int lane = tid & 31;
    const int wrp  = tid >> 5;
    const int b    = blockIdx.x;      // pixel id 0..1799
    const int n    = b / 900;
    const int rem  = b % 900;
    const int pi   = rem / 30, pj = rem % 30;

    const bool haspad = (pi < 4) | (pi > HH - 5) | (pj < 4) | (pj > WW - 5);

    // valid window rows/cols (in-image region of the 9x9 window)
    const int r0 = max(0, 4 - pi), r1 = min(8, 33 - pi);
    const int c0 = max(0, 4 - pj), c1 = min(8, 33 - pj);

    // ── phase 0: init class table ──
    // l = mh*10+mw; masked (mh==9||mw==9) -> 255; window-OOB -> 10; else 0.
    if (tid < 100) {
        int mh = tid / 10, mw = tid % 10;
        unsigned char cls = 255;
        if (mh < 9 && mw < 9) {
            bool inimg = (mh >= r0) & (mh <= r1) & (mw >= c0) & (mw <= c1);
            cls = inimg ? 0 : 10;
        }
        wtab.b[tid] = cls;
    }
    __syncthreads();

    // ── phase 1: one-hot scatter-write decode ──
    // k enumerates (plane c=1..9) x (slot s=0..80); val>0.5 -> write class.
    const float* xn = x + (long)n * 9000 + (pi - 4) * 30 + (pj - 4);
    #pragma unroll
    for (int it = 0; it < 6; it++) {
        int k = tid + it * 128;
        if (k < 729) {
            int c  = k / 81;              // 0..8 -> plane c+1
            int s  = k - 81 * c;
            int mh = s / 9, mw = s - 9 * mh;
            bool inimg = (mh >= r0) & (mh <= r1) & (mw >= c0) & (mw <= c1);
            if (inimg) {
                float val = xn[(c + 1) * 900 + mh * 30 + mw];
                if (val > 0.5f) wtab.b[mh * 10 + mw] = (unsigned char)(c + 1);
            }
        }
    }
    __syncthreads();

    // ── border pipeline on warp 0 ──
    if (haspad && wrp == 0) {
        const int d = lane;
        unsigned int word = (lane < 25) ? wtab.w[lane] : 0xFFFFFFFFu;

        // histogram via vcmp+popc+redux
        float hf[DD];
        #pragma unroll
        for (int c = 0; c < DD; c++) {
            unsigned int eq  = __vcmpeq4(word, c * 0x01010101u);
            int          cnt = __popc(eq) >> 3;
            hf[c] = (float)__reduce_add_sync(FULL, cnt);
        }

        // attention for the padding-class query; lane d owns dim d
        float num = 0.f, den = 0.f;
        if (d < DD) {
            float q10 = w_in[d * DD + 10];
            #pragma unroll
            for (int c = 0; c < DD; c++) {
                float k = w_in[(DD + d) * DD + c];
                float v = w_in[(2 * DD + d) * DD + c];
                float e = __expf(q10 * k) * hf[c];
                den += e;
                num += e * v;
            }
        }
        float ao = (d < DD) ? num / den : 0.f;

        // svec = e_10 + ao @ w_out^T
        float acc = (d == 10) ? 1.f : 0.f;
        #pragma unroll
        for (int c = 0; c < DD; c++) {
            float a = __shfl_sync(FULL, ao, c);
            if (d < DD) acc += a * w_out[d * DD + c];
        }
        float sv = (d < DD) ? acc : 0.f;

        // LN1
        float s1 = rsum16(sv);
        float s2 = rsum16(sv * sv);
        float m   = s1 * (1.f / 11.f);
        float var = fmaxf(s2 * (1.f / 11.f) - m * m, 0.f);
        float inv = rsqrtf(var + 1e-5f);
        float h1  = (d < DD) ? (sv - m) * inv * ln1_g[d] : 0.f;

        // FF
        float tt = rsum16((d < DD) ? h1 * w_ff1[d] : 0.f);
        tt = fmaxf(tt, 0.f);
        float h2 = (d < DD) ? h1 + tt * w_ff2[d] : 0.f;

        // LN2
        float t1 = rsum16(h2);
        float t2 = rsum16(h2 * h2);
        float m2   = t1 * (1.f / 11.f);
        float var2 = fmaxf(t2 * (1.f / 11.f) - m2 * m2, 0.f);
        float inv2 = rsqrtf(var2 + 1e-5f);
        float hhv  = (d < DD) ? (h2 - m2) * inv2 * ln2_g[d] : 0.f;

        // softmax over classes 0..9 (post-LN values bounded: no max-sub)
        float ex = (d < CC) ? __expf(hhv) : 0.f;
        float se = rsum16(ex);
        if (d < CC) pvs[d] = ex / se;
    }
    if (haspad) __syncthreads();   // uniform per block: legal

    // ── scatter 250 float4 across 128 threads (q = c*25 + j) ──
    float4* o4 = reinterpret_cast<float4*>(out + (long)b * 1000);
    #pragma unroll
    for (int it = 0; it < 2; it++) {
        int q = tid + it * 128;
        if (q < 250) {
            int c = q / 25;
            int j = q - c * 25;
            unsigned int wd = wtab.w[j];
            float        pc = haspad ? pvs[c] : 0.f;
            float4 r;
            float* rp = &r.x;
            #pragma unroll
            for (int e = 0; e < 4; e++) {
                unsigned int cls = (wd >> (8 * e)) & 0xFF;
                rp[e] = (cls == 10u) ? pc : ((cls == (unsigned)c) ? 1.0f : 0.0f);
            }
            o4[q] = r;
        }
    }
}

extern "C" void kernel_launch(void* const* d_in, const int* in_sizes, int n_in,
                              void* d_out, int out_size) {
    const float* x     = (const float*)d_in[0];
    const float* w_in  = (const float*)d_in[1];
    const float* w_out = (const float*)d_in[2];
    const float* w_ff1 = (const float*)d_in[3];
    const float* w_ff2 = (const float*)d_in[4];
    const float* ln1_g = (const float*)d_in[5];
    const float* ln2_g = (const float*)d_in[6];

    pve_kernel<<<1800, 128>>>(x, w_in, w_out, w_ff1, w_ff2, ln1_g, ln2_g,
                              (float*)d_out);
}